// round 1
// baseline (speedup 1.0000x reference)
#include <cuda_runtime.h>

// y = x @ w + b  (exact simplification of the memristor conductance model:
// g_pos - g_neg == g_eff and all K_V / k_g scale factors cancel).
//
// x: (128, 1024) f32   w: (1024, 512) f32   b: (512,) f32   out: (128, 512) f32
//
// Split-K GEMM: grid (32 n-tiles x 4 k-chunks) = 128 CTAs so all SMs get work.
// Deterministic: partials to static scratch, separate reduce kernel (no atomics).

#define NIN 1024
#define NOUT 512
#define BATCH 128

// 4 k-chunk partial results, 1 MB static scratch (allocation-free rule).
__device__ float g_partial[4 * BATCH * NOUT];

__global__ __launch_bounds__(256) void mm_partial_kernel(
    const float* __restrict__ X, const float* __restrict__ W)
{
    // Xs: 128 rows x 64 k, padded stride 65 so the 4 row-reads per thread hit
    // 4 distinct banks (4*65 = 260 == 4 mod 32). Ws: 64 k x 16 cols.
    __shared__ float Xs[128 * 65];
    __shared__ float Ws[64 * 16];

    const int t  = threadIdx.x;
    const int tr = t >> 3;          // 0..31  -> rows 4*tr .. 4*tr+3
    const int tc = t & 7;           // 0..7   -> cols 2*tc, 2*tc+1
    const int c0 = blockIdx.x * 16; // column tile base
    const int k0base = blockIdx.y * 256; // k-chunk base

    float acc[4][2] = {};

    for (int kt = 0; kt < 4; ++kt) {
        const int k0 = k0base + kt * 64;

        // Load X tile (128 x 64), gmem coalesced, smem conflict-free.
        #pragma unroll
        for (int i = 0; i < 32; ++i) {
            int idx = t + i * 256;      // 0..8191
            int r   = idx >> 6;
            int kk  = idx & 63;
            Xs[r * 65 + kk] = X[r * NIN + k0 + kk];
        }
        // Load W tile (64 x 16).
        #pragma unroll
        for (int i = 0; i < 4; ++i) {
            int idx = t + i * 256;      // 0..1023
            int kk  = idx >> 4;
            int c   = idx & 15;
            Ws[kk * 16 + c] = W[(k0 + kk) * NOUT + c0 + c];
        }
        __syncthreads();

        #pragma unroll 16
        for (int kk = 0; kk < 64; ++kk) {
            // broadcast float2 of the two columns this thread owns
            float2 wv = *reinterpret_cast<const float2*>(&Ws[kk * 16 + 2 * tc]);
            #pragma unroll
            for (int j = 0; j < 4; ++j) {
                float x = Xs[(4 * tr + j) * 65 + kk];
                acc[j][0] += x * wv.x;
                acc[j][1] += x * wv.y;
            }
        }
        __syncthreads();
    }

    float* part = g_partial + blockIdx.y * (BATCH * NOUT);
    #pragma unroll
    for (int j = 0; j < 4; ++j) {
        int r = 4 * tr + j;
        float2 v = make_float2(acc[j][0], acc[j][1]);
        *reinterpret_cast<float2*>(&part[r * NOUT + c0 + 2 * tc]) = v;
    }
}

__global__ __launch_bounds__(256) void reduce_bias_kernel(
    const float* __restrict__ B, float* __restrict__ out)
{
    int idx  = blockIdx.x * blockDim.x + threadIdx.x;  // 0..16383
    int base = idx * 4;                                // float4 per thread
    const float4 s0 = *reinterpret_cast<const float4*>(&g_partial[0 * BATCH * NOUT + base]);
    const float4 s1 = *reinterpret_cast<const float4*>(&g_partial[1 * BATCH * NOUT + base]);
    const float4 s2 = *reinterpret_cast<const float4*>(&g_partial[2 * BATCH * NOUT + base]);
    const float4 s3 = *reinterpret_cast<const float4*>(&g_partial[3 * BATCH * NOUT + base]);
    int col = base & (NOUT - 1);
    const float4 bv = *reinterpret_cast<const float4*>(&B[col]);
    float4 r;
    r.x = (s0.x + s1.x) + (s2.x + s3.x) + bv.x;
    r.y = (s0.y + s1.y) + (s2.y + s3.y) + bv.y;
    r.z = (s0.z + s1.z) + (s2.z + s3.z) + bv.z;
    r.w = (s0.w + s1.w) + (s2.w + s3.w) + bv.w;
    *reinterpret_cast<float4*>(&out[base]) = r;
}

extern "C" void kernel_launch(void* const* d_in, const int* in_sizes, int n_in,
                              void* d_out, int out_size)
{
    const float* X = (const float*)d_in[0];  // (128, 1024)
    const float* W = (const float*)d_in[1];  // (1024, 512)
    const float* B = (const float*)d_in[2];  // (512,)
    float* out = (float*)d_out;              // (128, 512)

    mm_partial_kernel<<<dim3(32, 4), 256>>>(X, W);
    reduce_bias_kernel<<<(BATCH * NOUT / 4) / 256, 256>>>(B, out);
}

// round 2
// speedup vs baseline: 1.1104x; 1.1104x over previous
#include <cuda_runtime.h>

// y = x @ w + b  (exact collapse of the memristor model: G_off cancels in the
// even-odd current subtraction, K_V and k_g cancel in the output rescale).
//
// x: (128,1024) f32   w: (1024,512) f32   b: (512,) f32   out: (128,512) f32
//
// Split-K GEMM, 128 CTAs = 8 col-tiles x 16 k-chunks. Per-CTA tile 128x64.
// Packed f32x2 FFMA (Blackwell): x row-pairs load packed straight from smem
// (k-major layout => rows contiguous), w duplicated into (w,w) pairs in smem.
// Deterministic: partials to static scratch, separate reduce (no atomics).

#define NIN 1024
#define NOUT 512
#define BATCH 128
#define KCHUNKS 16
#define KCHUNK 64
#define KSUB 32
#define CTILE 64
#define XS_STRIDE 130   // 128 rows + pad: even (8B align) & only 2-way store conflict

typedef unsigned long long u64t;

__device__ float g_partial[KCHUNKS * BATCH * NOUT];   // 16 x 64K partials

__device__ __forceinline__ u64t pack2(float lo, float hi) {
    u64t r;
    asm("mov.b64 %0, {%1, %2};" : "=l"(r) : "f"(lo), "f"(hi));
    return r;
}
__device__ __forceinline__ void unpack2(u64t v, float& lo, float& hi) {
    asm("mov.b64 {%0, %1}, %2;" : "=f"(lo), "=f"(hi) : "l"(v));
}
__device__ __forceinline__ u64t fma2(u64t a, u64t b, u64t c) {
    u64t d;
    asm("fma.rn.f32x2 %0, %1, %2, %3;" : "=l"(d) : "l"(a), "l"(b), "l"(c));
    return d;
}

__global__ __launch_bounds__(256) void mm_partial_kernel(
    const float* __restrict__ X, const float* __restrict__ W)
{
    __shared__ float Xs[KSUB * XS_STRIDE];   // [kk][row]  (k-major: rows contiguous)
    __shared__ u64t  Ws2[KSUB * CTILE];      // [kk][col]  duplicated (w,w) pairs

    const int t    = threadIdx.x;
    const int warp = t >> 5;
    const int lane = t & 31;
    const int half = lane >> 4;          // lanes 0-15 vs 16-31
    const int cl   = lane & 15;
    const int rbase = warp * 16 + half * 8;  // 8 rows per thread
    const int cbase = cl * 4;                // 4 cols per thread
    const int c0   = blockIdx.x * CTILE;
    const int kc0  = blockIdx.y * KCHUNK;

    u64t acc[4][4];                      // [row-pair][col], packed over row pairs
    #pragma unroll
    for (int i = 0; i < 4; ++i)
        #pragma unroll
        for (int j = 0; j < 4; ++j) acc[i][j] = 0ull;

    #pragma unroll 1
    for (int kt = 0; kt < KCHUNK / KSUB; ++kt) {
        const int k0 = kc0 + kt * KSUB;

        // X tile: 128 rows x 32 k. gmem coalesced (k contiguous per warp),
        // smem store stride 130 floats -> 2-way bank conflict only.
        #pragma unroll
        for (int i = 0; i < 16; ++i) {
            int idx = t + i * 256;          // 0..4095
            int kk  = idx & 31;
            int row = idx >> 5;
            Xs[kk * XS_STRIDE + row] = X[row * NIN + k0 + kk];
        }
        // W tile: 32 k x 64 cols, duplicated into packed pairs.
        #pragma unroll
        for (int i = 0; i < 8; ++i) {
            int idx = t + i * 256;          // 0..2047
            int col = idx & 63;
            int kk  = idx >> 6;
            float w = W[(k0 + kk) * NOUT + c0 + col];
            Ws2[kk * CTILE + col] = pack2(w, w);
        }
        __syncthreads();

        #pragma unroll
        for (int kk = 0; kk < KSUB; ++kk) {
            const u64t* xp = reinterpret_cast<const u64t*>(&Xs[kk * XS_STRIDE + rbase]);
            u64t x0 = xp[0], x1 = xp[1], x2 = xp[2], x3 = xp[3];  // 4 packed row-pairs
            const u64t* wp = &Ws2[kk * CTILE + cbase];
            #pragma unroll
            for (int c = 0; c < 4; ++c) {
                u64t w2 = wp[c];
                acc[0][c] = fma2(x0, w2, acc[0][c]);
                acc[1][c] = fma2(x1, w2, acc[1][c]);
                acc[2][c] = fma2(x2, w2, acc[2][c]);
                acc[3][c] = fma2(x3, w2, acc[3][c]);
            }
        }
        __syncthreads();
    }

    // Epilogue: unpack row pairs, write float4 rows (lanes contiguous -> coalesced)
    float* part = g_partial + blockIdx.y * (BATCH * NOUT);
    #pragma unroll
    for (int rp = 0; rp < 4; ++rp) {
        int r0 = rbase + 2 * rp;
        float lo[4], hi[4];
        #pragma unroll
        for (int c = 0; c < 4; ++c) unpack2(acc[rp][c], lo[c], hi[c]);
        *reinterpret_cast<float4*>(&part[r0 * NOUT + c0 + cbase]) =
            make_float4(lo[0], lo[1], lo[2], lo[3]);
        *reinterpret_cast<float4*>(&part[(r0 + 1) * NOUT + c0 + cbase]) =
            make_float4(hi[0], hi[1], hi[2], hi[3]);
    }
}

__global__ __launch_bounds__(128) void reduce_bias_kernel(
    const float* __restrict__ B, float* __restrict__ out)
{
    int idx  = blockIdx.x * 128 + threadIdx.x;   // 0..16383
    int base = idx * 4;
    // 16 independent LDG.128 -> full MLP, L2-resident scratch.
    float4 v[KCHUNKS];
    #pragma unroll
    for (int c = 0; c < KCHUNKS; ++c)
        v[c] = *reinterpret_cast<const float4*>(&g_partial[c * (BATCH * NOUT) + base]);

    // deterministic pairwise tree sum
    #pragma unroll
    for (int s = 1; s < KCHUNKS; s <<= 1)
        #pragma unroll
        for (int c = 0; c < KCHUNKS; c += 2 * s) {
            v[c].x += v[c + s].x; v[c].y += v[c + s].y;
            v[c].z += v[c + s].z; v[c].w += v[c + s].w;
        }

    int col = base & (NOUT - 1);
    float4 bv = *reinterpret_cast<const float4*>(&B[col]);
    float4 r = make_float4(v[0].x + bv.x, v[0].y + bv.y,
                           v[0].z + bv.z, v[0].w + bv.w);
    *reinterpret_cast<float4*>(&out[base]) = r;
}

extern "C" void kernel_launch(void* const* d_in, const int* in_sizes, int n_in,
                              void* d_out, int out_size)
{
    const float* X = (const float*)d_in[0];  // (128, 1024)
    const float* W = (const float*)d_in[1];  // (1024, 512)
    const float* B = (const float*)d_in[2];  // (512,)
    float* out = (float*)d_out;              // (128, 512)

    mm_partial_kernel<<<dim3(8, KCHUNKS), 256>>>(X, W);
    reduce_bias_kernel<<<(BATCH * NOUT / 4) / 128, 128>>>(B, out);
}

// round 3
// speedup vs baseline: 1.1296x; 1.0173x over previous
#include <cuda_runtime.h>

// y = x @ w + b  (exact collapse of the memristor model: G_off cancels in the
// even-odd current subtraction, K_V and k_g cancel in the output rescale).
//
// Single persistent kernel, 128 CTAs x 256 thr (all co-resident on 148 SMs):
//   phase 1: split-K GEMM partials (8 col-tiles x 16 k-chunks), f32x2 FFMA
//   software grid barrier (atomic ticket, wrap-safe across graph replays)
//   phase 2: reduce 16 partials + bias, scratch still hot in L2.

#define NIN 1024
#define NOUT 512
#define BATCH 128
#define KCHUNKS 16
#define KCHUNK 64
#define KSUB 32
#define CTILE 64
#define XS_STRIDE 130   // pad: 8B-aligned rows, <=2-way store conflicts

typedef unsigned long long u64t;

__device__ float g_partial[KCHUNKS * BATCH * NOUT];   // 4 MB scratch
__device__ unsigned g_bar;                            // monotonic barrier ticket

__device__ __forceinline__ u64t pack2(float lo, float hi) {
    u64t r; asm("mov.b64 %0, {%1, %2};" : "=l"(r) : "f"(lo), "f"(hi)); return r;
}
__device__ __forceinline__ void unpack2(u64t v, float& lo, float& hi) {
    asm("mov.b64 {%0, %1}, %2;" : "=f"(lo), "=f"(hi) : "l"(v));
}
__device__ __forceinline__ u64t fma2(u64t a, u64t b, u64t c) {
    u64t d; asm("fma.rn.f32x2 %0, %1, %2, %3;" : "=l"(d) : "l"(a), "l"(b), "l"(c));
    return d;
}

__global__ __launch_bounds__(256) void fused_kernel(
    const float* __restrict__ X, const float* __restrict__ W,
    const float* __restrict__ B, float* __restrict__ out)
{
    __shared__ float Xs[KSUB * XS_STRIDE];   // [kk][row] k-major: rows contiguous
    __shared__ u64t  Ws2[KSUB * CTILE];      // [kk][col] duplicated (w,w) pairs

    const int t    = threadIdx.x;
    const int bid  = blockIdx.x;             // 0..127
    const int warp = t >> 5;
    const int lane = t & 31;
    const int half = lane >> 4;
    const int cl   = lane & 15;
    const int rbase = warp * 16 + half * 8;  // 8 rows (4 packed pairs) per thread
    const int cbase = cl * 4;                // 4 cols per thread
    const int c0   = (bid & 7) * CTILE;
    const int kc0  = (bid >> 3) * KCHUNK;

    u64t acc[4][4];
    #pragma unroll
    for (int i = 0; i < 4; ++i)
        #pragma unroll
        for (int j = 0; j < 4; ++j) acc[i][j] = 0ull;

    // ---- gmem -> reg loads for one 32-k subchunk ----
    float4 xr[4], wr[2];
    auto load_regs = [&](int k0) {
        #pragma unroll
        for (int i = 0; i < 4; ++i) {            // X: 128 rows x 8 float4
            int idx = t + i * 256;               // 0..1023
            int kk4 = idx & 7, row = idx >> 3;
            xr[i] = *reinterpret_cast<const float4*>(&X[row * NIN + k0 + kk4 * 4]);
        }
        #pragma unroll
        for (int i = 0; i < 2; ++i) {            // W: 32 k x 16 float4
            int idx = t + i * 256;               // 0..511
            int c4 = idx & 15, kk = idx >> 4;
            wr[i] = *reinterpret_cast<const float4*>(&W[(k0 + kk) * NOUT + c0 + c4 * 4]);
        }
    };
    auto store_smem = [&]() {
        #pragma unroll
        for (int i = 0; i < 4; ++i) {
            int idx = t + i * 256;
            int kk4 = idx & 7, row = idx >> 3;
            Xs[(kk4 * 4 + 0) * XS_STRIDE + row] = xr[i].x;
            Xs[(kk4 * 4 + 1) * XS_STRIDE + row] = xr[i].y;
            Xs[(kk4 * 4 + 2) * XS_STRIDE + row] = xr[i].z;
            Xs[(kk4 * 4 + 3) * XS_STRIDE + row] = xr[i].w;
        }
        #pragma unroll
        for (int i = 0; i < 2; ++i) {
            int idx = t + i * 256;
            int c4 = idx & 15, kk = idx >> 4;
            u64t* wp = &Ws2[kk * CTILE + c4 * 4];
            wp[0] = pack2(wr[i].x, wr[i].x);
            wp[1] = pack2(wr[i].y, wr[i].y);
            wp[2] = pack2(wr[i].z, wr[i].z);
            wp[3] = pack2(wr[i].w, wr[i].w);
        }
    };
    auto compute = [&]() {
        #pragma unroll
        for (int kk = 0; kk < KSUB; ++kk) {
            const u64t* xp = reinterpret_cast<const u64t*>(&Xs[kk * XS_STRIDE + rbase]);
            u64t x0 = xp[0], x1 = xp[1], x2 = xp[2], x3 = xp[3];
            const u64t* wp = &Ws2[kk * CTILE + cbase];
            #pragma unroll
            for (int c = 0; c < 4; ++c) {
                u64t w2 = wp[c];
                acc[0][c] = fma2(x0, w2, acc[0][c]);
                acc[1][c] = fma2(x1, w2, acc[1][c]);
                acc[2][c] = fma2(x2, w2, acc[2][c]);
                acc[3][c] = fma2(x3, w2, acc[3][c]);
            }
        }
    };

    // ---- phase 1: pipelined split-K GEMM (2 subchunks) ----
    load_regs(kc0);
    store_smem();
    __syncthreads();
    load_regs(kc0 + KSUB);     // prefetch subchunk 1: latency hides under compute
    compute();
    __syncthreads();
    store_smem();
    __syncthreads();
    compute();

    float* part = g_partial + (bid >> 3) * (BATCH * NOUT);
    #pragma unroll
    for (int rp = 0; rp < 4; ++rp) {
        int r0 = rbase + 2 * rp;
        float lo[4], hi[4];
        #pragma unroll
        for (int c = 0; c < 4; ++c) unpack2(acc[rp][c], lo[c], hi[c]);
        *reinterpret_cast<float4*>(&part[r0 * NOUT + c0 + cbase]) =
            make_float4(lo[0], lo[1], lo[2], lo[3]);
        *reinterpret_cast<float4*>(&part[(r0 + 1) * NOUT + c0 + cbase]) =
            make_float4(hi[0], hi[1], hi[2], hi[3]);
    }

    // ---- grid barrier (all 128 CTAs co-resident; ticket is wrap-safe) ----
    __threadfence();            // release this thread's partial stores
    __syncthreads();
    if (t == 0) {
        unsigned old = atomicAdd(&g_bar, 1u);
        unsigned target = (old & ~127u) + 128u;
        while ((int)(*(volatile unsigned*)&g_bar - target) < 0) { }
    }
    __syncthreads();
    __threadfence();            // acquire

    // ---- phase 2: reduce 16 partials + bias (L2-hot) ----
    int gid = bid * 256 + t;                    // 0..32767
    if (gid < (BATCH * NOUT) / 4) {
        int base = gid * 4;
        float4 v[KCHUNKS];
        #pragma unroll
        for (int c = 0; c < KCHUNKS; ++c)
            v[c] = *reinterpret_cast<const float4*>(&g_partial[c * (BATCH * NOUT) + base]);
        #pragma unroll
        for (int s = 1; s < KCHUNKS; s <<= 1)
            #pragma unroll
            for (int c = 0; c < KCHUNKS; c += 2 * s) {
                v[c].x += v[c + s].x; v[c].y += v[c + s].y;
                v[c].z += v[c + s].z; v[c].w += v[c + s].w;
            }
        int col = base & (NOUT - 1);
        float4 bv = *reinterpret_cast<const float4*>(&B[col]);
        *reinterpret_cast<float4*>(&out[base]) =
            make_float4(v[0].x + bv.x, v[0].y + bv.y, v[0].z + bv.z, v[0].w + bv.w);
    }
}

extern "C" void kernel_launch(void* const* d_in, const int* in_sizes, int n_in,
                              void* d_out, int out_size)
{
    const float* X = (const float*)d_in[0];  // (128, 1024)
    const float* W = (const float*)d_in[1];  // (1024, 512)
    const float* B = (const float*)d_in[2];  // (512,)
    float* out = (float*)d_out;              // (128, 512)

    fused_kernel<<<128, 256>>>(X, W, B, out);
}

// round 4
// speedup vs baseline: 1.2023x; 1.0644x over previous
#include <cuda_runtime.h>

// y = x @ w + b  (exact collapse of the memristor model: G_off cancels in the
// even-odd current subtraction, K_V and k_g cancel in the output rescale).
//
// Single persistent kernel, 128 CTAs x 256 thr:
//   phase 1: split-K GEMM partials (8 col-tiles x 16 k-chunks), f32x2 FFMA
//            column map col = cl + 16*c  -> conflict-free broadcast W reads
//   grid barrier (atomic ticket, wrap-safe across graph replays)
//   phase 2: reduce 16 partials + bias, scratch L2-hot.

#define NIN 1024
#define NOUT 512
#define BATCH 128
#define KCHUNKS 16
#define KCHUNK 64
#define KSUB 32
#define CTILE 64
#define XS_STRIDE 132   // 528B rows: 16B-aligned (528 = 33*16) for LDS.128 x reads

typedef unsigned long long u64t;

__device__ float g_partial[KCHUNKS * BATCH * NOUT];   // 4 MB scratch
__device__ unsigned g_bar;                            // monotonic barrier ticket

__device__ __forceinline__ u64t pack2(float lo, float hi) {
    u64t r; asm("mov.b64 %0, {%1, %2};" : "=l"(r) : "f"(lo), "f"(hi)); return r;
}
__device__ __forceinline__ void unpack2(u64t v, float& lo, float& hi) {
    asm("mov.b64 {%0, %1}, %2;" : "=f"(lo), "=f"(hi) : "l"(v));
}
__device__ __forceinline__ u64t fma2(u64t a, u64t b, u64t c) {
    u64t d; asm("fma.rn.f32x2 %0, %1, %2, %3;" : "=l"(d) : "l"(a), "l"(b), "l"(c));
    return d;
}

__global__ __launch_bounds__(256) void fused_kernel(
    const float* __restrict__ X, const float* __restrict__ W,
    const float* __restrict__ B, float* __restrict__ out)
{
    __shared__ float Xs[KSUB * XS_STRIDE];   // [kk][row] k-major: rows contiguous
    __shared__ u64t  Ws2[KSUB * CTILE];      // [kk][col] duplicated (w,w) pairs

    const int t    = threadIdx.x;
    const int bid  = blockIdx.x;             // 0..127
    const int warp = t >> 5;
    const int lane = t & 31;
    const int half = lane >> 4;
    const int cl   = lane & 15;
    const int rbase = warp * 16 + half * 8;  // 8 rows (4 packed pairs) per thread
    const int c0   = (bid & 7) * CTILE;      // CTA column tile
    const int kc0  = (bid >> 3) * KCHUNK;    // CTA k-chunk

    u64t acc[4][4];                          // [row-pair][c], col = cl + 16*c
    #pragma unroll
    for (int i = 0; i < 4; ++i)
        #pragma unroll
        for (int j = 0; j < 4; ++j) acc[i][j] = 0ull;

    float4 xr[4], wr[2];
    auto load_regs = [&](int k0) {
        #pragma unroll
        for (int i = 0; i < 4; ++i) {            // X: 128 rows x 8 float4
            int idx = t + i * 256;
            int kk4 = idx & 7, row = idx >> 3;
            xr[i] = *reinterpret_cast<const float4*>(&X[row * NIN + k0 + kk4 * 4]);
        }
        #pragma unroll
        for (int i = 0; i < 2; ++i) {            // W: 32 k x 16 float4
            int idx = t + i * 256;
            int c4 = idx & 15, kk = idx >> 4;
            wr[i] = *reinterpret_cast<const float4*>(&W[(k0 + kk) * NOUT + c0 + c4 * 4]);
        }
    };
    auto store_smem = [&]() {
        #pragma unroll
        for (int i = 0; i < 4; ++i) {
            int idx = t + i * 256;
            int kk4 = idx & 7, row = idx >> 3;
            Xs[(kk4 * 4 + 0) * XS_STRIDE + row] = xr[i].x;
            Xs[(kk4 * 4 + 1) * XS_STRIDE + row] = xr[i].y;
            Xs[(kk4 * 4 + 2) * XS_STRIDE + row] = xr[i].z;
            Xs[(kk4 * 4 + 3) * XS_STRIDE + row] = xr[i].w;
        }
        #pragma unroll
        for (int i = 0; i < 2; ++i) {
            int idx = t + i * 256;
            int c4 = idx & 15, kk = idx >> 4;
            u64t* wp = &Ws2[kk * CTILE + c4 * 4];
            wp[0] = pack2(wr[i].x, wr[i].x);
            wp[1] = pack2(wr[i].y, wr[i].y);
            wp[2] = pack2(wr[i].z, wr[i].z);
            wp[3] = pack2(wr[i].w, wr[i].w);
        }
    };
    auto compute = [&]() {
        #pragma unroll
        for (int kk = 0; kk < KSUB; ++kk) {
            // x: 4 u64 row-pairs, 16B-aligned, 2 addresses/warp -> broadcast
            const u64t* xp = reinterpret_cast<const u64t*>(&Xs[kk * XS_STRIDE + rbase]);
            u64t x0 = xp[0], x1 = xp[1], x2 = xp[2], x3 = xp[3];
            // w: lanes 0-15 read 16 consecutive u64 (128B = all 32 banks once),
            // lanes 16-31 broadcast the same -> conflict-free
            const u64t* wrow = &Ws2[kk * CTILE];
            #pragma unroll
            for (int c = 0; c < 4; ++c) {
                u64t w2 = wrow[c * 16 + cl];
                acc[0][c] = fma2(x0, w2, acc[0][c]);
                acc[1][c] = fma2(x1, w2, acc[1][c]);
                acc[2][c] = fma2(x2, w2, acc[2][c]);
                acc[3][c] = fma2(x3, w2, acc[3][c]);
            }
        }
    };

    // ---- phase 1: pipelined split-K GEMM (2 subchunks) ----
    load_regs(kc0);
    store_smem();
    __syncthreads();
    load_regs(kc0 + KSUB);     // prefetch subchunk 1 under subchunk-0 compute
    compute();
    __syncthreads();
    store_smem();
    __syncthreads();
    compute();

    float* part = g_partial + (bid >> 3) * (BATCH * NOUT);
    #pragma unroll
    for (int rp = 0; rp < 4; ++rp) {
        int r0 = rbase + 2 * rp;
        #pragma unroll
        for (int c = 0; c < 4; ++c) {
            float lo, hi;
            unpack2(acc[rp][c], lo, hi);
            int col = c0 + c * 16 + cl;
            part[r0 * NOUT + col]       = lo;
            part[(r0 + 1) * NOUT + col] = hi;
        }
    }

    // ---- grid barrier (all 128 CTAs co-resident; ticket wrap-safe) ----
    __threadfence();
    __syncthreads();
    if (t == 0) {
        unsigned old = atomicAdd(&g_bar, 1u);
        unsigned target = (old & ~127u) + 128u;
        while ((int)(*(volatile unsigned*)&g_bar - target) < 0) { }
    }
    __syncthreads();
    __threadfence();

    // ---- phase 2: reduce 16 partials + bias (L2-hot) ----
    int gid = bid * 256 + t;                    // 0..32767
    if (gid < (BATCH * NOUT) / 4) {
        int base = gid * 4;
        float4 v[KCHUNKS];
        #pragma unroll
        for (int c = 0; c < KCHUNKS; ++c)
            v[c] = *reinterpret_cast<const float4*>(&g_partial[c * (BATCH * NOUT) + base]);
        #pragma unroll
        for (int s = 1; s < KCHUNKS; s <<= 1)
            #pragma unroll
            for (int c = 0; c < KCHUNKS; c += 2 * s) {
                v[c].x += v[c + s].x; v[c].y += v[c + s].y;
                v[c].z += v[c + s].z; v[c].w += v[c + s].w;
            }
        int col = base & (NOUT - 1);
        float4 bv = *reinterpret_cast<const float4*>(&B[col]);
        *reinterpret_cast<float4*>(&out[base]) =
            make_float4(v[0].x + bv.x, v[0].y + bv.y, v[0].z + bv.z, v[0].w + bv.w);
    }
}

extern "C" void kernel_launch(void* const* d_in, const int* in_sizes, int n_in,
                              void* d_out, int out_size)
{
    const float* X = (const float*)d_in[0];  // (128, 1024)
    const float* W = (const float*)d_in[1];  // (1024, 512)
    const float* B = (const float*)d_in[2];  // (512,)
    float* out = (float*)d_out;              // (128, 512)

    fused_kernel<<<128, 256>>>(X, W, B, out);
}

// round 6
// speedup vs baseline: 1.5706x; 1.3063x over previous
#include <cuda_runtime.h>
#include <cuda_bf16.h>
#include <cstdint>

// y = x @ w + b  (exact collapse of the memristor model; G_off / K_V / k_g all
// cancel).  3-term bf16-split GEMM on legacy mma.sync tensor cores (plain
// sm_100 target -- tcgen05 is 'a'-suffix only and the harness compiles sm_100):
//   y ~= xh@wh + xl@wh + xh@wl   (fp32 accum, rel err ~2^-16)
// Single fused kernel, 128 CTAs = 8 col-tiles x 16 k-chunks:
//   phase 1: per-CTA 128x64x64 HMMA GEMM   grid barrier   phase 2: L2 reduce.

#define NIN 1024
#define NOUT 512
#define BATCH 128
#define KCHUNKS 16
#define KCHUNK 64
#define CTILE 64

#define ASTRIDE 72            // bf16 elems per row (144 B) -> conflict-free frags
#define A_ROWS 128
#define B_ROWS 64

// dynamic smem (bf16 tiles)
#define OFF_AHI 0
#define OFF_ALO (OFF_AHI + A_ROWS * ASTRIDE)
#define OFF_BHI (OFF_ALO + A_ROWS * ASTRIDE)
#define OFF_BLO (OFF_BHI + B_ROWS * ASTRIDE)
#define SMEM_ELEMS (OFF_BLO + B_ROWS * ASTRIDE)
#define SMEM_BYTES (SMEM_ELEMS * 2)          // 55296 B

__device__ float g_partial[KCHUNKS * BATCH * NOUT];   // 4 MB scratch
__device__ unsigned g_bar;                            // monotonic ticket

__device__ __forceinline__ uint32_t packbf(float a, float b) {
    __nv_bfloat162 h = __floats2bfloat162_rn(a, b);   // a -> low 16 bits
    return *reinterpret_cast<uint32_t*>(&h);
}

__device__ __forceinline__ void mma_bf16(float* c, const uint32_t* a, const uint32_t* b) {
    asm volatile(
        "mma.sync.aligned.m16n8k16.row.col.f32.bf16.bf16.f32 "
        "{%0,%1,%2,%3}, {%4,%5,%6,%7}, {%8,%9}, {%0,%1,%2,%3};"
        : "+f"(c[0]), "+f"(c[1]), "+f"(c[2]), "+f"(c[3])
        : "r"(a[0]), "r"(a[1]), "r"(a[2]), "r"(a[3]), "r"(b[0]), "r"(b[1]));
}

__global__ __launch_bounds__(256) void fused_kernel(
    const float* __restrict__ X, const float* __restrict__ W,
    const float* __restrict__ B, float* __restrict__ out)
{
    extern __shared__ __nv_bfloat16 sm[];
    __nv_bfloat16* Ahi = sm + OFF_AHI;
    __nv_bfloat16* Alo = sm + OFF_ALO;
    __nv_bfloat16* Bhi = sm + OFF_BHI;
    __nv_bfloat16* Blo = sm + OFF_BLO;

    const int t = threadIdx.x, bid = blockIdx.x;
    const int warp = t >> 5, lane = t & 31;
    const int g  = lane >> 2;          // group row 0..7
    const int tq = lane & 3;           // thread-in-group 0..3
    const int c0  = (bid & 7) * CTILE;
    const int kc0 = (bid >> 3) * KCHUNK;

    // ---- fill A: X[128 x 64] -> hi/lo bf16 pairs along k (conflict-free) ----
    #pragma unroll
    for (int i = 0; i < 16; ++i) {
        int idx = t + i * 256;                 // 0..4095
        int kp = idx & 31, row = idx >> 5;     // per warp: row fixed, kp = lane
        float2 xv = *reinterpret_cast<const float2*>(&X[row * NIN + kc0 + 2 * kp]);
        float h0 = __bfloat162float(__float2bfloat16(xv.x));
        float h1 = __bfloat162float(__float2bfloat16(xv.y));
        *reinterpret_cast<uint32_t*>(&Ahi[row * ASTRIDE + 2 * kp]) = packbf(h0, h1);
        *reinterpret_cast<uint32_t*>(&Alo[row * ASTRIDE + 2 * kp]) = packbf(xv.x - h0, xv.y - h1);
    }
    // ---- fill B: W[64k x 64n] -> [n][k] hi/lo bf16 pairs along k ----
    #pragma unroll
    for (int i = 0; i < 8; ++i) {
        int idx = t + i * 256;                 // 0..2047
        int n = idx & 63, kp = idx >> 6;       // lanes: consecutive n -> coalesced
        float w0 = W[(kc0 + 2 * kp) * NOUT + c0 + n];
        float w1 = W[(kc0 + 2 * kp + 1) * NOUT + c0 + n];
        float h0 = __bfloat162float(__float2bfloat16(w0));
        float h1 = __bfloat162float(__float2bfloat16(w1));
        *reinterpret_cast<uint32_t*>(&Bhi[n * ASTRIDE + 2 * kp]) = packbf(h0, h1);
        *reinterpret_cast<uint32_t*>(&Blo[n * ASTRIDE + 2 * kp]) = packbf(w0 - h0, w1 - h1);
    }
    __syncthreads();

    // ---- phase 1 compute: warp owns rows 16w..16w+15, all 64 cols ----
    float acc[8][4];                   // 8 n-tiles x (c0..c3)
    #pragma unroll
    for (int j = 0; j < 8; ++j)
        #pragma unroll
        for (int q = 0; q < 4; ++q) acc[j][q] = 0.f;

    const int arow0 = (warp * 16 + g) * ASTRIDE;
    const int arow1 = arow0 + 8 * ASTRIDE;

    #pragma unroll
    for (int kk = 0; kk < 4; ++kk) {
        const int kb = kk * 16 + 2 * tq;       // fragment k base col
        uint32_t ah[4], al[4];
        ah[0] = *reinterpret_cast<const uint32_t*>(&Ahi[arow0 + kb]);
        ah[1] = *reinterpret_cast<const uint32_t*>(&Ahi[arow1 + kb]);
        ah[2] = *reinterpret_cast<const uint32_t*>(&Ahi[arow0 + kb + 8]);
        ah[3] = *reinterpret_cast<const uint32_t*>(&Ahi[arow1 + kb + 8]);
        al[0] = *reinterpret_cast<const uint32_t*>(&Alo[arow0 + kb]);
        al[1] = *reinterpret_cast<const uint32_t*>(&Alo[arow1 + kb]);
        al[2] = *reinterpret_cast<const uint32_t*>(&Alo[arow0 + kb + 8]);
        al[3] = *reinterpret_cast<const uint32_t*>(&Alo[arow1 + kb + 8]);

        uint32_t bh[8][2], bl[8][2];
        #pragma unroll
        for (int j = 0; j < 8; ++j) {
            const int brow = (8 * j + g) * ASTRIDE;
            bh[j][0] = *reinterpret_cast<const uint32_t*>(&Bhi[brow + kb]);
            bh[j][1] = *reinterpret_cast<const uint32_t*>(&Bhi[brow + kb + 8]);
            bl[j][0] = *reinterpret_cast<const uint32_t*>(&Blo[brow + kb]);
            bl[j][1] = *reinterpret_cast<const uint32_t*>(&Blo[brow + kb + 8]);
        }
        #pragma unroll
        for (int j = 0; j < 8; ++j) mma_bf16(acc[j], ah, bh[j]);
        #pragma unroll
        for (int j = 0; j < 8; ++j) mma_bf16(acc[j], al, bh[j]);
        #pragma unroll
        for (int j = 0; j < 8; ++j) mma_bf16(acc[j], ah, bl[j]);
    }

    // ---- store partials: c0,c1 -> (row g, cols 2t,2t+1); c2,c3 -> row g+8 ----
    {
        float* part = g_partial + (bid >> 3) * (BATCH * NOUT);
        const int r0 = warp * 16 + g;
        #pragma unroll
        for (int j = 0; j < 8; ++j) {
            const int col = c0 + 8 * j + 2 * tq;
            *reinterpret_cast<float2*>(&part[r0 * NOUT + col])       = make_float2(acc[j][0], acc[j][1]);
            *reinterpret_cast<float2*>(&part[(r0 + 8) * NOUT + col]) = make_float2(acc[j][2], acc[j][3]);
        }
    }

    // ---- grid barrier (128 co-resident CTAs; ticket wrap-safe) ----
    __threadfence();
    __syncthreads();
    if (t == 0) {
        unsigned old = atomicAdd(&g_bar, 1u);
        unsigned target = (old & ~127u) + 128u;
        while ((int)(*(volatile unsigned*)&g_bar - target) < 0) { }
    }
    __syncthreads();
    __threadfence();

    // ---- phase 2: reduce 16 partials + bias (L2-hot) ----
    int gid = bid * 256 + t;
    if (gid < (BATCH * NOUT) / 4) {
        int base = gid * 4;
        float4 v[KCHUNKS];
        #pragma unroll
        for (int c = 0; c < KCHUNKS; ++c)
            v[c] = *reinterpret_cast<const float4*>(&g_partial[c * (BATCH * NOUT) + base]);
        #pragma unroll
        for (int s = 1; s < KCHUNKS; s <<= 1)
            #pragma unroll
            for (int c = 0; c < KCHUNKS; c += 2 * s) {
                v[c].x += v[c + s].x; v[c].y += v[c + s].y;
                v[c].z += v[c + s].z; v[c].w += v[c + s].w;
            }
        int col = base & (NOUT - 1);
        float4 bv = *reinterpret_cast<const float4*>(&B[col]);
        *reinterpret_cast<float4*>(&out[base]) =
            make_float4(v[0].x + bv.x, v[0].y + bv.y, v[0].z + bv.z, v[0].w + bv.w);
    }
}

extern "C" void kernel_launch(void* const* d_in, const int* in_sizes, int n_in,
                              void* d_out, int out_size)
{
    const float* X = (const float*)d_in[0];  // (128, 1024)
    const float* W = (const float*)d_in[1];  // (1024, 512)
    const float* B = (const float*)d_in[2];  // (512,)
    float* out = (float*)d_out;              // (128, 512)

    cudaFuncSetAttribute(fused_kernel, cudaFuncAttributeMaxDynamicSharedMemorySize, SMEM_BYTES);
    fused_kernel<<<128, 256, SMEM_BYTES>>>(X, W, B, out);
}

// round 8
// speedup vs baseline: 1.6344x; 1.0406x over previous
#include <cuda_runtime.h>
#include <cuda_bf16.h>
#include <cstdint>

// y = x @ w + b  (exact collapse of the memristor model; G_off / K_V / k_g all
// cancel).  3-term bf16-split GEMM on legacy mma.sync tensor cores:
//   y ~= xh@wh + xl@wh + xh@wl   (fp32 accum, rel err ~2^-16)
// Single fused kernel, 128 CTAs x 512 thr = 8 col-tiles x 16 k-chunks:
//   phase 1: per-CTA 128x64x64 HMMA GEMM (16 warps, warp = 16 rows x 32 cols)
//   release/acquire grid barrier (CG pattern)
//   phase 2: scalar reduce over all 65536 threads + bias (L2-hot).

#define NIN 1024
#define NOUT 512
#define BATCH 128
#define KCHUNKS 16
#define KCHUNK 64
#define CTILE 64
#define NTHR 512

#define ASTRIDE 72            // bf16 elems per row (144 B) -> conflict-free frags
#define A_ROWS 128
#define B_ROWS 64

#define OFF_AHI 0
#define OFF_ALO (OFF_AHI + A_ROWS * ASTRIDE)
#define OFF_BHI (OFF_ALO + A_ROWS * ASTRIDE)
#define OFF_BLO (OFF_BHI + B_ROWS * ASTRIDE)
#define SMEM_ELEMS (OFF_BLO + B_ROWS * ASTRIDE)
#define SMEM_BYTES (SMEM_ELEMS * 2)          // 55296 B

__device__ float g_partial[KCHUNKS * BATCH * NOUT];   // 4 MB scratch
__device__ unsigned g_bar;                            // monotonic ticket

__device__ __forceinline__ uint32_t packbf(float a, float b) {
    __nv_bfloat162 h = __floats2bfloat162_rn(a, b);   // a -> low 16 bits
    return *reinterpret_cast<uint32_t*>(&h);
}
__device__ __forceinline__ uint64_t pack64(uint32_t lo, uint32_t hi) {
    uint64_t r; asm("mov.b64 %0, {%1, %2};" : "=l"(r) : "r"(lo), "r"(hi)); return r;
}
__device__ __forceinline__ void mma_bf16(float* c, const uint32_t* a, const uint32_t* b) {
    asm volatile(
        "mma.sync.aligned.m16n8k16.row.col.f32.bf16.bf16.f32 "
        "{%0,%1,%2,%3}, {%4,%5,%6,%7}, {%8,%9}, {%0,%1,%2,%3};"
        : "+f"(c[0]), "+f"(c[1]), "+f"(c[2]), "+f"(c[3])
        : "r"(a[0]), "r"(a[1]), "r"(a[2]), "r"(a[3]), "r"(b[0]), "r"(b[1]));
}

__global__ __launch_bounds__(NTHR) void fused_kernel(
    const float* __restrict__ X, const float* __restrict__ W,
    const float* __restrict__ B, float* __restrict__ out)
{
    extern __shared__ __nv_bfloat16 sm[];
    __nv_bfloat16* Ahi = sm + OFF_AHI;
    __nv_bfloat16* Alo = sm + OFF_ALO;
    __nv_bfloat16* Bhi = sm + OFF_BHI;
    __nv_bfloat16* Blo = sm + OFF_BLO;

    const int t = threadIdx.x, bid = blockIdx.x;
    const int warp = t >> 5, lane = t & 31;
    const int g  = lane >> 2;          // group row 0..7
    const int tq = lane & 3;           // thread-in-group 0..3
    const int c0  = (bid & 7) * CTILE;
    const int kc0 = (bid >> 3) * KCHUNK;

    // ---- fill A: X[128 x 64] -> hi/lo bf16.  128 rows x 16 float4 = 2048 slots
    //      = exactly 4 iterations of 512 threads (round-7 bug was i<8). ----
    #pragma unroll
    for (int i = 0; i < 4; ++i) {
        int idx = t + i * NTHR;                // 0..2047
        int kq = idx & 15, row = idx >> 4;     // row 0..127
        float4 xv = *reinterpret_cast<const float4*>(&X[row * NIN + kc0 + 4 * kq]);
        float h0 = __bfloat162float(__float2bfloat16(xv.x));
        float h1 = __bfloat162float(__float2bfloat16(xv.y));
        float h2 = __bfloat162float(__float2bfloat16(xv.z));
        float h3 = __bfloat162float(__float2bfloat16(xv.w));
        int e = row * ASTRIDE + 4 * kq;        // byte off 144*row+8*kq: 8B-aligned
        *reinterpret_cast<uint64_t*>(&Ahi[e]) = pack64(packbf(h0, h1), packbf(h2, h3));
        *reinterpret_cast<uint64_t*>(&Alo[e]) =
            pack64(packbf(xv.x - h0, xv.y - h1), packbf(xv.z - h2, xv.w - h3));
    }
    // ---- fill B: W[64k x 64n] -> [n][k] hi/lo bf16 pairs. 64n x 32kp = 2048. ----
    #pragma unroll
    for (int i = 0; i < 4; ++i) {
        int idx = t + i * NTHR;                // 0..2047
        int n = idx & 63, kp = idx >> 6;       // lanes: consecutive n -> coalesced
        float w0 = W[(kc0 + 2 * kp) * NOUT + c0 + n];
        float w1 = W[(kc0 + 2 * kp + 1) * NOUT + c0 + n];
        float h0 = __bfloat162float(__float2bfloat16(w0));
        float h1 = __bfloat162float(__float2bfloat16(w1));
        *reinterpret_cast<uint32_t*>(&Bhi[n * ASTRIDE + 2 * kp]) = packbf(h0, h1);
        *reinterpret_cast<uint32_t*>(&Blo[n * ASTRIDE + 2 * kp]) = packbf(w0 - h0, w1 - h1);
    }
    __syncthreads();

    // ---- phase 1 compute: warp = rows 16*(w>>1).., cols 32*(w&1).. ----
    float acc[4][4];
    #pragma unroll
    for (int j = 0; j < 4; ++j)
        #pragma unroll
        for (int q = 0; q < 4; ++q) acc[j][q] = 0.f;

    const int wr  = warp >> 1;
    const int cn0 = (warp & 1) * 32;
    const int arow0 = (wr * 16 + g) * ASTRIDE;
    const int arow1 = arow0 + 8 * ASTRIDE;

    #pragma unroll
    for (int kk = 0; kk < 4; ++kk) {
        const int kb = kk * 16 + 2 * tq;
        uint32_t ah[4], al[4];
        ah[0] = *reinterpret_cast<const uint32_t*>(&Ahi[arow0 + kb]);
        ah[1] = *reinterpret_cast<const uint32_t*>(&Ahi[arow1 + kb]);
        ah[2] = *reinterpret_cast<const uint32_t*>(&Ahi[arow0 + kb + 8]);
        ah[3] = *reinterpret_cast<const uint32_t*>(&Ahi[arow1 + kb + 8]);
        al[0] = *reinterpret_cast<const uint32_t*>(&Alo[arow0 + kb]);
        al[1] = *reinterpret_cast<const uint32_t*>(&Alo[arow1 + kb]);
        al[2] = *reinterpret_cast<const uint32_t*>(&Alo[arow0 + kb + 8]);
        al[3] = *reinterpret_cast<const uint32_t*>(&Alo[arow1 + kb + 8]);

        uint32_t bh[4][2], bl[4][2];
        #pragma unroll
        for (int j = 0; j < 4; ++j) {
            const int brow = (cn0 + 8 * j + g) * ASTRIDE;
            bh[j][0] = *reinterpret_cast<const uint32_t*>(&Bhi[brow + kb]);
            bh[j][1] = *reinterpret_cast<const uint32_t*>(&Bhi[brow + kb + 8]);
            bl[j][0] = *reinterpret_cast<const uint32_t*>(&Blo[brow + kb]);
            bl[j][1] = *reinterpret_cast<const uint32_t*>(&Blo[brow + kb + 8]);
        }
        #pragma unroll
        for (int j = 0; j < 4; ++j) mma_bf16(acc[j], ah, bh[j]);
        #pragma unroll
        for (int j = 0; j < 4; ++j) mma_bf16(acc[j], al, bh[j]);
        #pragma unroll
        for (int j = 0; j < 4; ++j) mma_bf16(acc[j], ah, bl[j]);
    }

    // ---- store partials ----
    {
        float* part = g_partial + (bid >> 3) * (BATCH * NOUT);
        const int r0 = wr * 16 + g;
        #pragma unroll
        for (int j = 0; j < 4; ++j) {
            const int col = c0 + cn0 + 8 * j + 2 * tq;
            *reinterpret_cast<float2*>(&part[r0 * NOUT + col])       = make_float2(acc[j][0], acc[j][1]);
            *reinterpret_cast<float2*>(&part[(r0 + 8) * NOUT + col]) = make_float2(acc[j][2], acc[j][3]);
        }
    }

    // ---- grid barrier: CG release/acquire pattern ----
    __syncthreads();
    if (t == 0) {
        unsigned my;
        asm volatile("atom.add.release.gpu.global.u32 %0, [%1], 1;"
                     : "=r"(my) : "l"(&g_bar) : "memory");
        unsigned target = (my & ~127u) + 128u;
        unsigned cur;
        do {
            asm volatile("ld.acquire.gpu.global.u32 %0, [%1];"
                         : "=r"(cur) : "l"(&g_bar) : "memory");
        } while ((int)(cur - target) < 0);
    }
    __syncthreads();

    // ---- phase 2: scalar reduce, all 65536 threads, L2-hot ----
    {
        int gid = bid * NTHR + t;              // 0..65535 == BATCH*NOUT
        float v[KCHUNKS];
        #pragma unroll
        for (int c = 0; c < KCHUNKS; ++c)
            v[c] = g_partial[c * (BATCH * NOUT) + gid];
        #pragma unroll
        for (int s = 1; s < KCHUNKS; s <<= 1)
            #pragma unroll
            for (int c = 0; c < KCHUNKS; c += 2 * s)
                v[c] += v[c + s];
        out[gid] = v[0] + B[gid & (NOUT - 1)];
    }
}

extern "C" void kernel_launch(void* const* d_in, const int* in_sizes, int n_in,
                              void* d_out, int out_size)
{
    const float* X = (const float*)d_in[0];  // (128, 1024)
    const float* W = (const float*)d_in[1];  // (1024, 512)
    const float* B = (const float*)d_in[2];  // (512,)
    float* out = (float*)d_out;              // (128, 512)

    cudaFuncSetAttribute(fused_kernel, cudaFuncAttributeMaxDynamicSharedMemorySize, SMEM_BYTES);
    fused_kernel<<<128, NTHR, SMEM_BYTES>>>(X, W, B, out);
}